// round 2
// baseline (speedup 1.0000x reference)
#include <cuda_runtime.h>
#include <mma.h>
#include <cfloat>

using namespace nvcuda;

// Problem: img_feats [4096, 4096] fp32.
//   x    = feats / 64                     (sqrt(4096) = 64)
//   sims = x @ x.T      = feats @ feats.T / 4096
//   sims[i][i] = -inf ; attn = softmax(sims, axis=-1)
//   out  = attn @ x.T   = attn @ feats.T / 64
//
// Both GEMMs are C = A @ B^T with row-major A [M,K] and row-major B [N,K].

constexpr int NMAT = 4096;
constexpr int BM = 128, BN = 128, BK = 32;
constexpr int SKEW = 4;  // smem row padding (floats), keeps ldm % 4 == 0

// Scratch for sims/attn (64 MB). Static __device__ array: allocation-free.
__device__ float g_sims[(size_t)NMAT * NMAT];

// ---------------------------------------------------------------------------
// GEMM: C = alpha * (A @ B^T), A row-major [4096,4096], B row-major [4096,4096]
// PASSES==1: plain TF32. PASSES==3: 3xTF32 split (hi*hi + hi*lo + lo*hi),
// recovering ~fp32 input precision on the tensor pipe.
// Block tile 128x128, 8 warps (2x4), warp tile 64x32 = 4x2 wmma 16x16 tiles.
// ---------------------------------------------------------------------------
template <int PASSES>
__global__ __launch_bounds__(256, 1)
void gemm_abt(const float* __restrict__ A, const float* __restrict__ B,
              float* __restrict__ C, float alpha)
{
    __shared__ float As[BM][BK + SKEW];
    __shared__ float Bs[BN][BK + SKEW];

    const int tid  = threadIdx.x;
    const int warp = tid >> 5;
    const int wm   = (warp >> 2) * 64;  // warp row offset within block tile
    const int wn   = (warp & 3) * 32;   // warp col offset within block tile
    const int rowBase = blockIdx.y * BM;
    const int colBase = blockIdx.x * BN;

    wmma::fragment<wmma::accumulator, 16, 16, 8, float> acc[4][2];
#pragma unroll
    for (int i = 0; i < 4; i++)
#pragma unroll
        for (int j = 0; j < 2; j++)
            wmma::fill_fragment(acc[i][j], 0.0f);

    for (int k0 = 0; k0 < NMAT; k0 += BK) {
        // Stage A and B tiles: 128 rows x 32 cols each, float4 loads.
        // 128*8 = 1024 float4 per tile, 256 threads -> 4 each.
#pragma unroll
        for (int l = 0; l < 4; l++) {
            int idx = tid + l * 256;
            int r   = idx >> 3;
            int c4  = (idx & 7) << 2;
            *(float4*)&As[r][c4] =
                *(const float4*)&A[(size_t)(rowBase + r) * NMAT + k0 + c4];
            *(float4*)&Bs[r][c4] =
                *(const float4*)&B[(size_t)(colBase + r) * NMAT + k0 + c4];
        }
        __syncthreads();

#pragma unroll
        for (int kk = 0; kk < BK; kk += 8) {
            wmma::fragment<wmma::matrix_a, 16, 16, 8, wmma::precision::tf32,
                           wmma::row_major> a_hi[4], a_lo[4];
            wmma::fragment<wmma::matrix_b, 16, 16, 8, wmma::precision::tf32,
                           wmma::col_major> b_hi[2], b_lo[2];

#pragma unroll
            for (int i = 0; i < 4; i++) {
                wmma::load_matrix_sync(a_hi[i], &As[wm + 16 * i][kk], BK + SKEW);
#pragma unroll
                for (int t = 0; t < a_hi[i].num_elements; t++) {
                    float v  = a_hi[i].x[t];
                    float hi = wmma::__float_to_tf32(v);
                    if constexpr (PASSES == 3)
                        a_lo[i].x[t] = wmma::__float_to_tf32(v - hi);
                    a_hi[i].x[t] = hi;
                }
            }
#pragma unroll
            for (int j = 0; j < 2; j++) {
                // matrix_b col_major over Bs[n][k] gives the B^T operand.
                wmma::load_matrix_sync(b_hi[j], &Bs[wn + 16 * j][kk], BK + SKEW);
#pragma unroll
                for (int t = 0; t < b_hi[j].num_elements; t++) {
                    float v  = b_hi[j].x[t];
                    float hi = wmma::__float_to_tf32(v);
                    if constexpr (PASSES == 3)
                        b_lo[j].x[t] = wmma::__float_to_tf32(v - hi);
                    b_hi[j].x[t] = hi;
                }
            }

#pragma unroll
            for (int i = 0; i < 4; i++)
#pragma unroll
                for (int j = 0; j < 2; j++) {
                    if constexpr (PASSES == 3) {
                        wmma::mma_sync(acc[i][j], a_lo[i], b_hi[j], acc[i][j]);
                        wmma::mma_sync(acc[i][j], a_hi[i], b_lo[j], acc[i][j]);
                    }
                    wmma::mma_sync(acc[i][j], a_hi[i], b_hi[j], acc[i][j]);
                }
        }
        __syncthreads();
    }

    // Epilogue: scale and store.
#pragma unroll
    for (int i = 0; i < 4; i++)
#pragma unroll
        for (int j = 0; j < 2; j++) {
#pragma unroll
            for (int t = 0; t < acc[i][j].num_elements; t++)
                acc[i][j].x[t] *= alpha;
            wmma::store_matrix_sync(
                &C[(size_t)(rowBase + wm + 16 * i) * NMAT + colBase + wn + 16 * j],
                acc[i][j], NMAT, wmma::mem_row_major);
        }
}

// ---------------------------------------------------------------------------
// Row softmax with diagonal mask, in place. One block per row, 256 threads,
// 16 values per thread held in registers.
// ---------------------------------------------------------------------------
__global__ __launch_bounds__(256)
void softmax_rows(float* __restrict__ S)
{
    const int row = blockIdx.x;
    const int tid = threadIdx.x;
    float* p = S + (size_t)row * NMAT;

    float v[16];
    float m = -FLT_MAX;
#pragma unroll
    for (int i = 0; i < 16; i++) {
        int j = tid + i * 256;
        v[i] = p[j];
        if (j != row) m = fmaxf(m, v[i]);
    }

    __shared__ float red[256];
    red[tid] = m;
    __syncthreads();
#pragma unroll
    for (int s = 128; s > 0; s >>= 1) {
        if (tid < s) red[tid] = fmaxf(red[tid], red[tid + s]);
        __syncthreads();
    }
    m = red[0];
    __syncthreads();

    float sum = 0.0f;
#pragma unroll
    for (int i = 0; i < 16; i++) {
        int j = tid + i * 256;
        float e = (j == row) ? 0.0f : __expf(v[i] - m);
        v[i] = e;
        sum += e;
    }
    red[tid] = sum;
    __syncthreads();
#pragma unroll
    for (int s = 128; s > 0; s >>= 1) {
        if (tid < s) red[tid] += red[tid + s];
        __syncthreads();
    }
    const float inv = 1.0f / red[0];
#pragma unroll
    for (int i = 0; i < 16; i++)
        p[tid + i * 256] = v[i] * inv;
}

// ---------------------------------------------------------------------------
extern "C" void kernel_launch(void* const* d_in, const int* in_sizes, int n_in,
                              void* d_out, int out_size)
{
    const float* feats = (const float*)d_in[0];
    float* out = (float*)d_out;

    float* sims = nullptr;
    cudaGetSymbolAddress((void**)&sims, g_sims);  // host-side query, capture-safe

    dim3 grid(NMAT / BN, NMAT / BM);  // (32, 32)

    // sims = feats @ feats^T / 4096   (single-pass TF32: softmax is
    // offset-invariant; abs error ~1e-5 -> negligible in attn)
    gemm_abt<1><<<grid, 256>>>(feats, feats, sims, 1.0f / 4096.0f);

    // row softmax with diag mask, in place
    softmax_rows<<<NMAT, 256>>>(sims);

    // out = attn @ feats^T / 64       (3xTF32: output has heavy cancellation,
    // single-pass TF32 would be ~7e-4 rel err -- too close to the 1e-3 gate)
    gemm_abt<3><<<grid, 256>>>(sims, feats, out, 1.0f / 64.0f);
}

// round 4
// speedup vs baseline: 5.2970x; 5.2970x over previous
#include <cuda_runtime.h>
#include <cuda_bf16.h>
#include <cfloat>
#include <cstdint>

// ===========================================================================
// SimpleAttention 4096x4096, sm_103 (plain target: tcgen05 unavailable, so
// legacy tensor path mma.sync.m16n8k16.bf16 + ldmatrix + cp.async pipeline).
//   x    = feats / 64
//   sims = x @ x^T            GEMM1: single-pass bf16 (softmax offset-invariant)
//   attn = softmax(sims, diag masked)
//   out  = attn @ x^T         GEMM2: 3-pass bf16 split (Ah*Bh + Ah*Bl + Al*Bh)
// Both GEMMs: C = A @ B^T, A[m][k] and B[n][k] row-major ("TN" layout).
// ===========================================================================

constexpr int NMAT = 4096;
constexpr int BM = 128, BN = 128, BK = 64;     // CTA tile; BK in bf16 elems
constexpr int NSTEPS = NMAT / BK;              // 64
constexpr int TILEB = BM * 128;                // bytes per operand tile (row=128B)

// ---- device scratch (allocation-free) -------------------------------------
__device__ float          g_sims[(size_t)NMAT * NMAT];  // 64 MB
__device__ __nv_bfloat16  g_xh[(size_t)NMAT * NMAT];    // 32 MB each
__device__ __nv_bfloat16  g_xl[(size_t)NMAT * NMAT];
__device__ __nv_bfloat16  g_ah[(size_t)NMAT * NMAT];
__device__ __nv_bfloat16  g_al[(size_t)NMAT * NMAT];

// ---- helpers --------------------------------------------------------------
#define SWZ(o) ((o) ^ (((o) >> 3) & 0x70))   // SW128 swizzle on byte offsets

__device__ __forceinline__ uint32_t smem_u32(const void* p) {
    uint32_t a;
    asm("{ .reg .u64 t; cvta.to.shared.u64 t, %1; cvt.u32.u64 %0, t; }"
        : "=r"(a) : "l"(p));
    return a;
}

__device__ __forceinline__ void cp_async16(uint32_t dst, const void* src) {
    asm volatile("cp.async.cg.shared.global [%0], [%1], 16;"
                 :: "r"(dst), "l"(src));
}
__device__ __forceinline__ void cp_commit() {
    asm volatile("cp.async.commit_group;" ::: "memory");
}
template <int N>
__device__ __forceinline__ void cp_wait() {
    asm volatile("cp.async.wait_group %0;" :: "n"(N) : "memory");
}

__device__ __forceinline__ void ldsm_x4(uint32_t addr, uint32_t r[4]) {
    asm volatile("ldmatrix.sync.aligned.m8n8.x4.shared.b16 {%0,%1,%2,%3}, [%4];"
                 : "=r"(r[0]), "=r"(r[1]), "=r"(r[2]), "=r"(r[3]) : "r"(addr));
}

__device__ __forceinline__ void mma_bf16(float d[4], const uint32_t a[4],
                                         uint32_t b0, uint32_t b1) {
    asm volatile(
        "mma.sync.aligned.m16n8k16.row.col.f32.bf16.bf16.f32 "
        "{%0,%1,%2,%3}, {%4,%5,%6,%7}, {%8,%9}, {%0,%1,%2,%3};"
        : "+f"(d[0]), "+f"(d[1]), "+f"(d[2]), "+f"(d[3])
        : "r"(a[0]), "r"(a[1]), "r"(a[2]), "r"(a[3]), "r"(b0), "r"(b1));
}

// ===========================================================================
// C[128x128 tile] = alpha * A @ B^T.
// PASSES==1: C = Ah Bh^T.  PASSES==3: C = Ah Bh^T + Ah Bl^T + Al Bh^T.
// ===========================================================================
template <int PASSES>
__global__ __launch_bounds__(256, 1)
void gemm_mma(const __nv_bfloat16* __restrict__ Ah,
              const __nv_bfloat16* __restrict__ Al,
              const __nv_bfloat16* __restrict__ Bh,
              const __nv_bfloat16* __restrict__ Bl,
              float* __restrict__ C, float alpha)
{
    constexpr int OFF_AL   = TILEB;                       // only if PASSES==3
    constexpr int OFF_BH   = (PASSES == 3) ? 2 * TILEB : TILEB;
    constexpr int OFF_BL   = 3 * TILEB;
    constexpr int STAGE    = (PASSES == 3) ? 4 * TILEB : 2 * TILEB;
    constexpr int NSTAGE   = (PASSES == 3) ? 2 : 4;       // 128 KB smem both

    extern __shared__ char smem[];
    const uint32_t sbase = smem_u32(smem);

    const int tid  = threadIdx.x;
    const int warp = tid >> 5;
    const int lane = tid & 31;
    const int wm   = (warp & 3) * 32;   // warp row offset in tile
    const int wn   = (warp >> 2) * 64;  // warp col offset in tile
    const int rowBase = blockIdx.y * BM;
    const int colBase = blockIdx.x * BN;

    const size_t rowB = (size_t)NMAT * 2;  // gmem bytes per row
    const char* gAh = (const char*)(Ah + (size_t)rowBase * NMAT);
    const char* gAl = (const char*)(Al + (size_t)rowBase * NMAT);
    const char* gBh = (const char*)(Bh + (size_t)colBase * NMAT);
    const char* gBl = (const char*)(Bl + (size_t)colBase * NMAT);

    // ldmatrix per-thread address components (x4 covering a 16x16 bf16 block)
    // A frag: m = (lane&7) + ((lane>>3)&1)*8 ; k byte off = ((lane>>4)&1)*16
    // B frag: n = (lane&7) + ((lane>>4)&1)*8 ; k byte off = ((lane>>3)&1)*16
    const int mA  = (lane & 7) + ((lane >> 3) & 1) * 8;
    const int kAo = ((lane >> 4) & 1) * 16;
    const int nB  = (lane & 7) + ((lane >> 4) & 1) * 8;
    const int kBo = ((lane >> 3) & 1) * 16;

    float acc[2][8][4];
#pragma unroll
    for (int i = 0; i < 2; i++)
#pragma unroll
        for (int j = 0; j < 8; j++)
#pragma unroll
            for (int t = 0; t < 4; t++) acc[i][j][t] = 0.0f;

    auto load_stage = [&](int kt) {
        if (kt < NSTEPS) {
            const uint32_t st = sbase + (kt % NSTAGE) * STAGE;
            const size_t kOff = (size_t)kt * 128;  // 64 bf16 = 128 bytes
#pragma unroll
            for (int l = 0; l < 4; l++) {          // A rows: 128 x 8 chunks
                const int i = tid + l * 256;
                const int r = i >> 3, c = (i & 7) << 4;
                const uint32_t sw = SWZ(r * 128 + c);
                const size_t g = (size_t)r * rowB + kOff + c;
                cp_async16(st + sw, gAh + g);
                if constexpr (PASSES == 3) cp_async16(st + OFF_AL + sw, gAl + g);
            }
#pragma unroll
            for (int l = 0; l < 4; l++) {          // B rows
                const int i = tid + l * 256;
                const int r = i >> 3, c = (i & 7) << 4;
                const uint32_t sw = SWZ(r * 128 + c);
                const size_t g = (size_t)r * rowB + kOff + c;
                cp_async16(st + OFF_BH + sw, gBh + g);
                if constexpr (PASSES == 3) cp_async16(st + OFF_BL + sw, gBl + g);
            }
        }
        cp_commit();  // commit even when empty: uniform group accounting
    };

    // Prologue: stages 0 .. NSTAGE-2
#pragma unroll
    for (int s = 0; s < NSTAGE - 1; s++) load_stage(s);

    for (int kt = 0; kt < NSTEPS; kt++) {
        cp_wait<NSTAGE - 2>();   // stage kt resident (this thread's groups)
        __syncthreads();         // visible to all; all warps done with kt-1
        load_stage(kt + NSTAGE - 1);

        const uint32_t st = sbase + (kt % NSTAGE) * STAGE;
#pragma unroll
        for (int ck = 0; ck < 4; ck++) {           // 4 x k16 chunks
            const int kb = ck * 32;                // bytes along K

            uint32_t a_hi[2][4], a_lo[2][4];
#pragma unroll
            for (int mi = 0; mi < 2; mi++) {
                const int row = wm + mi * 16 + mA;
                ldsm_x4(st + SWZ(row * 128 + kb + kAo), a_hi[mi]);
                if constexpr (PASSES == 3)
                    ldsm_x4(st + OFF_AL + SWZ(row * 128 + kb + kAo), a_lo[mi]);
            }
            uint32_t b_hi[4][4], b_lo[4][4];
#pragma unroll
            for (int nb = 0; nb < 4; nb++) {
                const int row = wn + nb * 16 + nB;
                ldsm_x4(st + OFF_BH + SWZ(row * 128 + kb + kBo), b_hi[nb]);
                if constexpr (PASSES == 3)
                    ldsm_x4(st + OFF_BL + SWZ(row * 128 + kb + kBo), b_lo[nb]);
            }

#pragma unroll
            for (int mi = 0; mi < 2; mi++)
#pragma unroll
                for (int nb = 0; nb < 4; nb++)
#pragma unroll
                    for (int h = 0; h < 2; h++) {
                        float* d = acc[mi][nb * 2 + h];
                        mma_bf16(d, a_hi[mi], b_hi[nb][2 * h], b_hi[nb][2 * h + 1]);
                        if constexpr (PASSES == 3) {
                            mma_bf16(d, a_hi[mi], b_lo[nb][2 * h], b_lo[nb][2 * h + 1]);
                            mma_bf16(d, a_lo[mi], b_hi[nb][2 * h], b_hi[nb][2 * h + 1]);
                        }
                    }
        }
    }

    // Epilogue: c0,c1 -> (row, col..col+1); c2,c3 -> (row+8, same cols)
    const int rq = lane >> 2, cq = (lane & 3) * 2;
#pragma unroll
    for (int mi = 0; mi < 2; mi++) {
        const int row0 = rowBase + wm + mi * 16 + rq;
#pragma unroll
        for (int nj = 0; nj < 8; nj++) {
            const int col = colBase + wn + nj * 8 + cq;
            float2 v0 = make_float2(acc[mi][nj][0] * alpha, acc[mi][nj][1] * alpha);
            float2 v1 = make_float2(acc[mi][nj][2] * alpha, acc[mi][nj][3] * alpha);
            *(float2*)&C[(size_t)row0 * NMAT + col]       = v0;
            *(float2*)&C[(size_t)(row0 + 8) * NMAT + col] = v1;
        }
    }
}

// ===========================================================================
// feats -> (hi, lo) bf16 split.  4 floats per thread.
// ===========================================================================
__global__ __launch_bounds__(256)
void split_bf16(const float* __restrict__ x,
                __nv_bfloat16* __restrict__ h, __nv_bfloat16* __restrict__ l)
{
    const size_t i = (size_t)blockIdx.x * blockDim.x + threadIdx.x;
    const float4 v = ((const float4*)x)[i];
    __nv_bfloat16 h0 = __float2bfloat16(v.x), h1 = __float2bfloat16(v.y);
    __nv_bfloat16 h2 = __float2bfloat16(v.z), h3 = __float2bfloat16(v.w);
    __nv_bfloat162* hp = (__nv_bfloat162*)h;
    __nv_bfloat162* lp = (__nv_bfloat162*)l;
    hp[2 * i]     = __nv_bfloat162(h0, h1);
    hp[2 * i + 1] = __nv_bfloat162(h2, h3);
    lp[2 * i]     = __nv_bfloat162(__float2bfloat16(v.x - __bfloat162float(h0)),
                                   __float2bfloat16(v.y - __bfloat162float(h1)));
    lp[2 * i + 1] = __nv_bfloat162(__float2bfloat16(v.z - __bfloat162float(h2)),
                                   __float2bfloat16(v.w - __bfloat162float(h3)));
}

// ===========================================================================
// Row softmax with diag mask; emits attn as bf16 hi/lo split directly.
// ===========================================================================
__global__ __launch_bounds__(256)
void softmax_rows(const float* __restrict__ S,
                  __nv_bfloat16* __restrict__ ah, __nv_bfloat16* __restrict__ al)
{
    const int row = blockIdx.x;
    const int tid = threadIdx.x;
    const float* p = S + (size_t)row * NMAT;

    float v[16];
    float m = -FLT_MAX;
#pragma unroll
    for (int i = 0; i < 16; i++) {
        const int j = tid + i * 256;
        v[i] = p[j];
        if (j != row) m = fmaxf(m, v[i]);
    }

    __shared__ float red[256];
    red[tid] = m;
    __syncthreads();
#pragma unroll
    for (int s = 128; s > 0; s >>= 1) {
        if (tid < s) red[tid] = fmaxf(red[tid], red[tid + s]);
        __syncthreads();
    }
    m = red[0];
    __syncthreads();

    float sum = 0.0f;
#pragma unroll
    for (int i = 0; i < 16; i++) {
        const int j = tid + i * 256;
        const float e = (j == row) ? 0.0f : __expf(v[i] - m);
        v[i] = e;
        sum += e;
    }
    red[tid] = sum;
    __syncthreads();
#pragma unroll
    for (int s = 128; s > 0; s >>= 1) {
        if (tid < s) red[tid] += red[tid + s];
        __syncthreads();
    }
    const float inv = 1.0f / red[0];

    __nv_bfloat16* arow_h = ah + (size_t)row * NMAT;
    __nv_bfloat16* arow_l = al + (size_t)row * NMAT;
#pragma unroll
    for (int i = 0; i < 16; i++) {
        const int j = tid + i * 256;
        const float a = v[i] * inv;
        const __nv_bfloat16 h = __float2bfloat16(a);
        arow_h[j] = h;
        arow_l[j] = __float2bfloat16(a - __bfloat162float(h));
    }
}

// ===========================================================================
extern "C" void kernel_launch(void* const* d_in, const int* in_sizes, int n_in,
                              void* d_out, int out_size)
{
    const float* feats = (const float*)d_in[0];
    float* out = (float*)d_out;

    float* sims;
    __nv_bfloat16 *xh, *xl, *ah, *al;
    cudaGetSymbolAddress((void**)&sims, g_sims);
    cudaGetSymbolAddress((void**)&xh, g_xh);
    cudaGetSymbolAddress((void**)&xl, g_xl);
    cudaGetSymbolAddress((void**)&ah, g_ah);
    cudaGetSymbolAddress((void**)&al, g_al);

    constexpr int SMEM1 = 4 * (2 * TILEB);  // 4 stages x 32 KB = 128 KB
    constexpr int SMEM3 = 2 * (4 * TILEB);  // 2 stages x 64 KB = 128 KB
    cudaFuncSetAttribute(gemm_mma<1>, cudaFuncAttributeMaxDynamicSharedMemorySize, SMEM1);
    cudaFuncSetAttribute(gemm_mma<3>, cudaFuncAttributeMaxDynamicSharedMemorySize, SMEM3);

    // 1) split feats into bf16 hi/lo
    split_bf16<<<(NMAT * (size_t)NMAT / 4) / 256, 256>>>(feats, xh, xl);

    dim3 grid(NMAT / BN, NMAT / BM);  // (32, 32)

    // 2) sims = feats @ feats^T / 4096  (single-pass bf16)
    gemm_mma<1><<<grid, 256, SMEM1>>>(xh, nullptr, xh, nullptr, sims, 1.0f / 4096.0f);

    // 3) softmax rows (diag masked), emit attn hi/lo bf16
    softmax_rows<<<NMAT, 256>>>(sims, ah, al);

    // 4) out = attn @ feats^T / 64  (3-pass bf16 split)
    gemm_mma<3><<<grid, 256, SMEM3>>>(ah, al, xh, xl, out, 1.0f / 64.0f);
}

// round 6
// speedup vs baseline: 10.3913x; 1.9617x over previous
#include <cuda_runtime.h>
#include <cuda_fp16.h>
#include <cfloat>
#include <cstdint>

// ===========================================================================
// SimpleAttention 4096x4096, sm_103 legacy tensor path (tcgen05 not available
// on the plain sm_103 PTX target): mma.sync.m16n8k16.f16 + ldmatrix + cp.async.
//   sims = feats @ feats^T / 4096     GEMM1: 1-pass fp16  (softmax offset-inv)
//   attn = softmax(sims, diag masked) -> fp16
//   out  = attn @ feats^T / 64        GEMM2: 1-pass fp16  (rel err ~4e-4)
// Both GEMMs: C = alpha * A @ B^T, A[m][k], B[n][k] row-major fp16.
// CTA tile 128x128 (4 warps, warp tile 64x64), BK=64, 3-stage cp.async,
// 2 CTAs/SM.
// ===========================================================================

constexpr int NMAT = 4096;
constexpr int BK = 64;                    // k-tile in fp16 elems (128 bytes)
constexpr int NSTEPS = NMAT / BK;         // 64
constexpr int TILEB = 128 * 128;          // bytes per operand tile (128 rows x 128B)
constexpr int STAGE = 2 * TILEB;          // A + B = 32 KB
constexpr int NSTAGE = 3;                 // 96 KB smem
constexpr int SMEM_TOTAL = NSTAGE * STAGE;

// ---- device scratch (allocation-free) -------------------------------------
__device__ float  g_sims[(size_t)NMAT * NMAT];  // 64 MB
__device__ __half g_xh[(size_t)NMAT * NMAT];    // 32 MB: fp16(feats)
__device__ __half g_ah[(size_t)NMAT * NMAT];    // 32 MB: fp16(attn)

// ---- helpers --------------------------------------------------------------
#define SWZ(o) ((o) ^ (((o) >> 3) & 0x70))   // SW128 swizzle on byte offsets

__device__ __forceinline__ uint32_t smem_u32(const void* p) {
    uint32_t a;
    asm("{ .reg .u64 t; cvta.to.shared.u64 t, %1; cvt.u32.u64 %0, t; }"
        : "=r"(a) : "l"(p));
    return a;
}
__device__ __forceinline__ void cp_async16(uint32_t dst, const void* src) {
    asm volatile("cp.async.cg.shared.global [%0], [%1], 16;"
                 :: "r"(dst), "l"(src));
}
__device__ __forceinline__ void cp_commit() {
    asm volatile("cp.async.commit_group;" ::: "memory");
}
template <int N>
__device__ __forceinline__ void cp_wait() {
    asm volatile("cp.async.wait_group %0;" :: "n"(N) : "memory");
}
__device__ __forceinline__ void ldsm_x4(uint32_t addr, uint32_t r[4]) {
    asm volatile("ldmatrix.sync.aligned.m8n8.x4.shared.b16 {%0,%1,%2,%3}, [%4];"
                 : "=r"(r[0]), "=r"(r[1]), "=r"(r[2]), "=r"(r[3]) : "r"(addr));
}
__device__ __forceinline__ void mma_f16(float d[4], const uint32_t a[4],
                                        uint32_t b0, uint32_t b1) {
    asm volatile(
        "mma.sync.aligned.m16n8k16.row.col.f32.f16.f16.f32 "
        "{%0,%1,%2,%3}, {%4,%5,%6,%7}, {%8,%9}, {%0,%1,%2,%3};"
        : "+f"(d[0]), "+f"(d[1]), "+f"(d[2]), "+f"(d[3])
        : "r"(a[0]), "r"(a[1]), "r"(a[2]), "r"(a[3]), "r"(b0), "r"(b1));
}

// ===========================================================================
// C[128x128 tile] = alpha * A @ B^T, fp16 inputs, fp32 accum.
// 4 warps; warp tile 64x64 = 4 (m16) x 8 (n8) mma fragments.
// ===========================================================================
__global__ __launch_bounds__(128, 2)
void gemm_f16(const __half* __restrict__ A, const __half* __restrict__ B,
              float* __restrict__ C, float alpha)
{
    extern __shared__ char smem[];
    const uint32_t sbase = smem_u32(smem);

    const int tid  = threadIdx.x;
    const int warp = tid >> 5;
    const int lane = tid & 31;
    const int wm   = (warp & 1) * 64;   // warp row offset in CTA tile
    const int wn   = (warp >> 1) * 64;  // warp col offset in CTA tile
    const int rowBase = blockIdx.y * 128;
    const int colBase = blockIdx.x * 128;

    const size_t rowB = (size_t)NMAT * 2;  // gmem bytes per row
    const char* gA = (const char*)(A + (size_t)rowBase * NMAT);
    const char* gB = (const char*)(B + (size_t)colBase * NMAT);

    // ldmatrix x4 per-thread addressing within a 16x16 fp16 block
    const int mA  = (lane & 7) + ((lane >> 3) & 1) * 8;   // A: m row
    const int kAo = ((lane >> 4) & 1) * 16;               // A: k byte offset
    const int nB  = (lane & 7) + ((lane >> 4) & 1) * 8;   // B: n row
    const int kBo = ((lane >> 3) & 1) * 16;               // B: k byte offset

    float acc[4][8][4];
#pragma unroll
    for (int i = 0; i < 4; i++)
#pragma unroll
        for (int j = 0; j < 8; j++)
#pragma unroll
            for (int t = 0; t < 4; t++) acc[i][j][t] = 0.0f;

    auto load_stage = [&](int kt) {
        if (kt < NSTEPS) {
            const uint32_t st = sbase + (kt % NSTAGE) * STAGE;
            const size_t kOff = (size_t)kt * 128;  // 64 fp16 = 128 bytes
#pragma unroll
            for (int l = 0; l < 8; l++) {          // A: 128 rows x 8 chunks
                const int i = tid + l * 128;
                const int r = i >> 3, c = (i & 7) << 4;
                cp_async16(st + SWZ(r * 128 + c),
                           gA + (size_t)r * rowB + kOff + c);
            }
#pragma unroll
            for (int l = 0; l < 8; l++) {          // B: 128 rows x 8 chunks
                const int i = tid + l * 128;
                const int r = i >> 3, c = (i & 7) << 4;
                cp_async16(st + TILEB + SWZ(r * 128 + c),
                           gB + (size_t)r * rowB + kOff + c);
            }
        }
        cp_commit();  // uniform group accounting even when empty
    };

    // Prologue: stages 0, 1
    load_stage(0);
    load_stage(1);

    for (int kt = 0; kt < NSTEPS; kt++) {
        cp_wait<NSTAGE - 2>();
        __syncthreads();
        load_stage(kt + NSTAGE - 1);

        const uint32_t st = sbase + (kt % NSTAGE) * STAGE;
#pragma unroll
        for (int ck = 0; ck < 4; ck++) {          // 4 x k16 chunks
            const int kb = ck * 32;               // bytes along K

            uint32_t a[4][4];
#pragma unroll
            for (int mi = 0; mi < 4; mi++) {
                const int row = wm + mi * 16 + mA;
                ldsm_x4(st + SWZ(row * 128 + kb + kAo), a[mi]);
            }
            uint32_t b[4][4];
#pragma unroll
            for (int nb = 0; nb < 4; nb++) {
                const int row = wn + nb * 16 + nB;
                ldsm_x4(st + TILEB + SWZ(row * 128 + kb + kBo), b[nb]);
            }

#pragma unroll
            for (int mi = 0; mi < 4; mi++)
#pragma unroll
                for (int nb = 0; nb < 4; nb++)
#pragma unroll
                    for (int h = 0; h < 2; h++)
                        mma_f16(acc[mi][nb * 2 + h], a[mi],
                                b[nb][2 * h], b[nb][2 * h + 1]);
        }
    }

    // Epilogue
    const int rq = lane >> 2, cq = (lane & 3) * 2;
#pragma unroll
    for (int mi = 0; mi < 4; mi++) {
        const int row0 = rowBase + wm + mi * 16 + rq;
#pragma unroll
        for (int nj = 0; nj < 8; nj++) {
            const int col = colBase + wn + nj * 8 + cq;
            float2 v0 = make_float2(acc[mi][nj][0] * alpha, acc[mi][nj][1] * alpha);
            float2 v1 = make_float2(acc[mi][nj][2] * alpha, acc[mi][nj][3] * alpha);
            *(float2*)&C[(size_t)row0 * NMAT + col]       = v0;
            *(float2*)&C[(size_t)(row0 + 8) * NMAT + col] = v1;
        }
    }
}

// ===========================================================================
// feats fp32 -> fp16
// ===========================================================================
__global__ __launch_bounds__(256)
void conv_f16(const float* __restrict__ x, __half* __restrict__ h)
{
    const size_t i = (size_t)blockIdx.x * blockDim.x + threadIdx.x;
    const float4 v = ((const float4*)x)[i];
    __half2* hp = (__half2*)h;
    hp[2 * i]     = __half2(__float2half(v.x), __float2half(v.y));
    hp[2 * i + 1] = __half2(__float2half(v.z), __float2half(v.w));
}

// ===========================================================================
// Row softmax with diag mask; emits attn as fp16.
// ===========================================================================
__global__ __launch_bounds__(256)
void softmax_rows(const float* __restrict__ S, __half* __restrict__ ah)
{
    const int row = blockIdx.x;
    const int tid = threadIdx.x;
    const float* p = S + (size_t)row * NMAT;

    float v[16];
    float m = -FLT_MAX;
#pragma unroll
    for (int i = 0; i < 16; i++) {
        const int j = tid + i * 256;
        v[i] = p[j];
        if (j != row) m = fmaxf(m, v[i]);
    }

    __shared__ float red[256];
    red[tid] = m;
    __syncthreads();
#pragma unroll
    for (int s = 128; s > 0; s >>= 1) {
        if (tid < s) red[tid] = fmaxf(red[tid], red[tid + s]);
        __syncthreads();
    }
    m = red[0];
    __syncthreads();

    float sum = 0.0f;
#pragma unroll
    for (int i = 0; i < 16; i++) {
        const int j = tid + i * 256;
        const float e = (j == row) ? 0.0f : __expf(v[i] - m);
        v[i] = e;
        sum += e;
    }
    red[tid] = sum;
    __syncthreads();
#pragma unroll
    for (int s = 128; s > 0; s >>= 1) {
        if (tid < s) red[tid] += red[tid + s];
        __syncthreads();
    }
    const float inv = 1.0f / red[0];

    __half* arow = ah + (size_t)row * NMAT;
#pragma unroll
    for (int i = 0; i < 16; i++) {
        const int j = tid + i * 256;
        arow[j] = __float2half(v[i] * inv);
    }
}

// ===========================================================================
extern "C" void kernel_launch(void* const* d_in, const int* in_sizes, int n_in,
                              void* d_out, int out_size)
{
    const float* feats = (const float*)d_in[0];
    float* out = (float*)d_out;

    float* sims;
    __half *xh, *ah;
    cudaGetSymbolAddress((void**)&sims, g_sims);
    cudaGetSymbolAddress((void**)&xh, g_xh);
    cudaGetSymbolAddress((void**)&ah, g_ah);

    cudaFuncSetAttribute(gemm_f16, cudaFuncAttributeMaxDynamicSharedMemorySize,
                         SMEM_TOTAL);

    // 1) feats -> fp16
    conv_f16<<<(NMAT * (size_t)NMAT / 4) / 256, 256>>>(feats, xh);

    dim3 grid(NMAT / 128, NMAT / 128);  // (32, 32)

    // 2) sims = feats @ feats^T / 4096
    gemm_f16<<<grid, 128, SMEM_TOTAL>>>(xh, xh, sims, 1.0f / 4096.0f);

    // 3) softmax rows (diag masked) -> fp16 attn
    softmax_rows<<<NMAT, 256>>>(sims, ah);

    // 4) out = attn @ feats^T / 64
    gemm_f16<<<grid, 128, SMEM_TOTAL>>>(ah, xh, out, 1.0f / 64.0f);
}

// round 7
// speedup vs baseline: 12.9545x; 1.2467x over previous
#include <cuda_runtime.h>
#include <cuda_fp16.h>
#include <cfloat>
#include <cstdint>

// ===========================================================================
// SimpleAttention 4096x4096, sm_103 legacy tensor path (tcgen05 is not
// available on the plain sm_103 PTX target the harness uses).
//   sims = feats @ feats^T / 4096   GEMM1: 1-pass fp16, SYMMETRIC -> compute
//                                   only upper-triangular tiles, mirror-write.
//   attn = softmax(sims, diag masked) -> fp16
//   out  = attn @ feats^T / 64      GEMM2: 1-pass fp16 (full)
// GEMM: C = alpha * A @ B^T, A[m][k], B[n][k] row-major fp16.
// CTA tile 128x128 (4 warps, 64x64 warp tile), BK=64, 3-stage cp.async,
// 2 CTAs/SM.
// ===========================================================================

constexpr int NMAT = 4096;
constexpr int BK = 64;                    // k-tile in fp16 elems (128 bytes)
constexpr int NSTEPS = NMAT / BK;         // 64
constexpr int TILEB = 128 * 128;          // bytes per operand tile
constexpr int STAGE = 2 * TILEB;          // A + B = 32 KB
constexpr int NSTAGE = 3;                 // 96 KB smem
constexpr int SMEM_TOTAL = NSTAGE * STAGE;
constexpr int TPAD = 132;                 // transpose buffer row stride (floats)

// ---- device scratch (allocation-free) -------------------------------------
__device__ float  g_sims[(size_t)NMAT * NMAT];  // 64 MB
__device__ __half g_xh[(size_t)NMAT * NMAT];    // fp16(feats)
__device__ __half g_ah[(size_t)NMAT * NMAT];    // fp16(attn)

// ---- helpers --------------------------------------------------------------
#define SWZ(o) ((o) ^ (((o) >> 3) & 0x70))   // SW128 swizzle on byte offsets

__device__ __forceinline__ uint32_t smem_u32(const void* p) {
    uint32_t a;
    asm("{ .reg .u64 t; cvta.to.shared.u64 t, %1; cvt.u32.u64 %0, t; }"
        : "=r"(a) : "l"(p));
    return a;
}
__device__ __forceinline__ void cp_async16(uint32_t dst, const void* src) {
    asm volatile("cp.async.cg.shared.global [%0], [%1], 16;"
                 :: "r"(dst), "l"(src));
}
__device__ __forceinline__ void cp_commit() {
    asm volatile("cp.async.commit_group;" ::: "memory");
}
template <int N>
__device__ __forceinline__ void cp_wait() {
    asm volatile("cp.async.wait_group %0;" :: "n"(N) : "memory");
}
__device__ __forceinline__ void ldsm_x4(uint32_t addr, uint32_t r[4]) {
    asm volatile("ldmatrix.sync.aligned.m8n8.x4.shared.b16 {%0,%1,%2,%3}, [%4];"
                 : "=r"(r[0]), "=r"(r[1]), "=r"(r[2]), "=r"(r[3]) : "r"(addr));
}
__device__ __forceinline__ void mma_f16(float d[4], const uint32_t a[4],
                                        uint32_t b0, uint32_t b1) {
    asm volatile(
        "mma.sync.aligned.m16n8k16.row.col.f32.f16.f16.f32 "
        "{%0,%1,%2,%3}, {%4,%5,%6,%7}, {%8,%9}, {%0,%1,%2,%3};"
        : "+f"(d[0]), "+f"(d[1]), "+f"(d[2]), "+f"(d[3])
        : "r"(a[0]), "r"(a[1]), "r"(a[2]), "r"(a[3]), "r"(b0), "r"(b1));
}

// ===========================================================================
// C[128x128 tile] = alpha * A @ B^T, fp16 in, fp32 accum.
// MIRROR: only tiles with by <= bx are computed; off-diagonal tiles are also
// written transposed at the mirrored location (C symmetric).
// ===========================================================================
template <bool MIRROR>
__global__ __launch_bounds__(128, 2)
void gemm_f16(const __half* __restrict__ A, const __half* __restrict__ B,
              float* __restrict__ C, float alpha)
{
    if (MIRROR && blockIdx.y > blockIdx.x) return;  // lower triangle: skip

    extern __shared__ char smem[];
    const uint32_t sbase = smem_u32(smem);

    const int tid  = threadIdx.x;
    const int warp = tid >> 5;
    const int lane = tid & 31;
    const int wm   = (warp & 1) * 64;
    const int wn   = (warp >> 1) * 64;
    const int rowBase = blockIdx.y * 128;
    const int colBase = blockIdx.x * 128;

    const size_t rowB = (size_t)NMAT * 2;
    const char* gA = (const char*)(A + (size_t)rowBase * NMAT);
    const char* gB = (const char*)(B + (size_t)colBase * NMAT);

    const int mA  = (lane & 7) + ((lane >> 3) & 1) * 8;
    const int kAo = ((lane >> 4) & 1) * 16;
    const int nB  = (lane & 7) + ((lane >> 4) & 1) * 8;
    const int kBo = ((lane >> 3) & 1) * 16;

    float acc[4][8][4];
#pragma unroll
    for (int i = 0; i < 4; i++)
#pragma unroll
        for (int j = 0; j < 8; j++)
#pragma unroll
            for (int t = 0; t < 4; t++) acc[i][j][t] = 0.0f;

    auto load_stage = [&](int kt) {
        if (kt < NSTEPS) {
            const uint32_t st = sbase + (kt % NSTAGE) * STAGE;
            const size_t kOff = (size_t)kt * 128;
#pragma unroll
            for (int l = 0; l < 8; l++) {
                const int i = tid + l * 128;
                const int r = i >> 3, c = (i & 7) << 4;
                cp_async16(st + SWZ(r * 128 + c),
                           gA + (size_t)r * rowB + kOff + c);
            }
#pragma unroll
            for (int l = 0; l < 8; l++) {
                const int i = tid + l * 128;
                const int r = i >> 3, c = (i & 7) << 4;
                cp_async16(st + TILEB + SWZ(r * 128 + c),
                           gB + (size_t)r * rowB + kOff + c);
            }
        }
        cp_commit();
    };

    load_stage(0);
    load_stage(1);

    for (int kt = 0; kt < NSTEPS; kt++) {
        cp_wait<NSTAGE - 2>();
        __syncthreads();
        load_stage(kt + NSTAGE - 1);

        const uint32_t st = sbase + (kt % NSTAGE) * STAGE;
#pragma unroll
        for (int ck = 0; ck < 4; ck++) {
            const int kb = ck * 32;

            uint32_t a[4][4];
#pragma unroll
            for (int mi = 0; mi < 4; mi++) {
                const int row = wm + mi * 16 + mA;
                ldsm_x4(st + SWZ(row * 128 + kb + kAo), a[mi]);
            }
            uint32_t b[4][4];
#pragma unroll
            for (int nb = 0; nb < 4; nb++) {
                const int row = wn + nb * 16 + nB;
                ldsm_x4(st + TILEB + SWZ(row * 128 + kb + kBo), b[nb]);
            }

#pragma unroll
            for (int mi = 0; mi < 4; mi++)
#pragma unroll
                for (int nb = 0; nb < 4; nb++)
#pragma unroll
                    for (int h = 0; h < 2; h++)
                        mma_f16(acc[mi][nb * 2 + h], a[mi],
                                b[nb][2 * h], b[nb][2 * h + 1]);
        }
    }

    // ---- scale once ----
#pragma unroll
    for (int mi = 0; mi < 4; mi++)
#pragma unroll
        for (int nj = 0; nj < 8; nj++)
#pragma unroll
            for (int t = 0; t < 4; t++) acc[mi][nj][t] *= alpha;

    // ---- normal store ----
    const int rq = lane >> 2, cq = (lane & 3) * 2;
#pragma unroll
    for (int mi = 0; mi < 4; mi++) {
        const int row0 = rowBase + wm + mi * 16 + rq;
#pragma unroll
        for (int nj = 0; nj < 8; nj++) {
            const int col = colBase + wn + nj * 8 + cq;
            *(float2*)&C[(size_t)row0 * NMAT + col] =
                make_float2(acc[mi][nj][0], acc[mi][nj][1]);
            *(float2*)&C[(size_t)(row0 + 8) * NMAT + col] =
                make_float2(acc[mi][nj][2], acc[mi][nj][3]);
        }
    }

    // ---- mirror store (transpose via smem) for off-diagonal tiles ----
    if (MIRROR && blockIdx.x != blockIdx.y) {
        __syncthreads();  // all warps done reading the last stage
        float* T = (float*)smem;  // [128][TPAD]; 128*132*4 = 67.6 KB <= 96 KB
#pragma unroll
        for (int mi = 0; mi < 4; mi++) {
            const int r0 = wm + mi * 16 + rq;
#pragma unroll
            for (int nj = 0; nj < 8; nj++) {
                const int c0 = wn + nj * 8 + cq;
                T[(c0 + 0) * TPAD + r0]     = acc[mi][nj][0];
                T[(c0 + 1) * TPAD + r0]     = acc[mi][nj][1];
                T[(c0 + 0) * TPAD + r0 + 8] = acc[mi][nj][2];
                T[(c0 + 1) * TPAD + r0 + 8] = acc[mi][nj][3];
            }
        }
        __syncthreads();
        // coalesced write: mirror tile row r' = original column colBase + r'
#pragma unroll 4
        for (int rb = 0; rb < 128; rb += 4) {
            const int rr = rb + warp;                      // row within tile
            const float4 v = *(const float4*)&T[rr * TPAD + (lane << 2)];
            *(float4*)&C[(size_t)(colBase + rr) * NMAT + rowBase + (lane << 2)] = v;
        }
    }
}

// ===========================================================================
// feats fp32 -> fp16
// ===========================================================================
__global__ __launch_bounds__(256)
void conv_f16(const float* __restrict__ x, __half* __restrict__ h)
{
    const size_t i = (size_t)blockIdx.x * blockDim.x + threadIdx.x;
    const float4 v = ((const float4*)x)[i];
    __half2* hp = (__half2*)h;
    hp[2 * i]     = __half2(__float2half(v.x), __float2half(v.y));
    hp[2 * i + 1] = __half2(__float2half(v.z), __float2half(v.w));
}

// ===========================================================================
// Row softmax with diag mask; emits attn as fp16.
// ===========================================================================
__global__ __launch_bounds__(256)
void softmax_rows(const float* __restrict__ S, __half* __restrict__ ah)
{
    const int row = blockIdx.x;
    const int tid = threadIdx.x;
    const float* p = S + (size_t)row * NMAT;

    float v[16];
    float m = -FLT_MAX;
#pragma unroll
    for (int i = 0; i < 16; i++) {
        const int j = tid + i * 256;
        v[i] = p[j];
        if (j != row) m = fmaxf(m, v[i]);
    }

    __shared__ float red[256];
    red[tid] = m;
    __syncthreads();
#pragma unroll
    for (int s = 128; s > 0; s >>= 1) {
        if (tid < s) red[tid] = fmaxf(red[tid], red[tid + s]);
        __syncthreads();
    }
    m = red[0];
    __syncthreads();

    float sum = 0.0f;
#pragma unroll
    for (int i = 0; i < 16; i++) {
        const int j = tid + i * 256;
        const float e = (j == row) ? 0.0f : __expf(v[i] - m);
        v[i] = e;
        sum += e;
    }
    red[tid] = sum;
    __syncthreads();
#pragma unroll
    for (int s = 128; s > 0; s >>= 1) {
        if (tid < s) red[tid] += red[tid + s];
        __syncthreads();
    }
    const float inv = 1.0f / red[0];

    __half* arow = ah + (size_t)row * NMAT;
#pragma unroll
    for (int i = 0; i < 16; i++) {
        const int j = tid + i * 256;
        arow[j] = __float2half(v[i] * inv);
    }
}

// ===========================================================================
extern "C" void kernel_launch(void* const* d_in, const int* in_sizes, int n_in,
                              void* d_out, int out_size)
{
    const float* feats = (const float*)d_in[0];
    float* out = (float*)d_out;

    float* sims;
    __half *xh, *ah;
    cudaGetSymbolAddress((void**)&sims, g_sims);
    cudaGetSymbolAddress((void**)&xh, g_xh);
    cudaGetSymbolAddress((void**)&ah, g_ah);

    cudaFuncSetAttribute(gemm_f16<true>,
                         cudaFuncAttributeMaxDynamicSharedMemorySize, SMEM_TOTAL);
    cudaFuncSetAttribute(gemm_f16<false>,
                         cudaFuncAttributeMaxDynamicSharedMemorySize, SMEM_TOTAL);

    // 1) feats -> fp16
    conv_f16<<<(NMAT * (size_t)NMAT / 4) / 256, 256>>>(feats, xh);

    dim3 grid(NMAT / 128, NMAT / 128);  // (32, 32)

    // 2) sims = feats @ feats^T / 4096  (symmetric: upper tiles + mirror)
    gemm_f16<true><<<grid, 128, SMEM_TOTAL>>>(xh, xh, sims, 1.0f / 4096.0f);

    // 3) softmax rows (diag masked) -> fp16 attn
    softmax_rows<<<NMAT, 256>>>(sims, ah);

    // 4) out = attn @ feats^T / 64  (full)
    gemm_f16<false><<<grid, 128, SMEM_TOTAL>>>(ah, xh, out, 1.0f / 64.0f);
}

// round 8
// speedup vs baseline: 13.2299x; 1.0213x over previous
#include <cuda_runtime.h>
#include <cuda_fp16.h>
#include <cfloat>
#include <cstdint>

// ===========================================================================
// SimpleAttention 4096x4096, sm_103 legacy tensor path (tcgen05 unavailable
// on the plain sm_103 PTX target the harness uses).
//   sims = feats @ feats^T / 4096   GEMM1: 1-pass fp16, symmetric -> upper
//                                   tiles + mirror write; sims stored fp16.
//   attn = softmax(sims, diag masked) -> fp16
//   out  = attn @ feats^T / 64      GEMM2: 1-pass fp16 (full), fp32 out.
// GEMM: C = alpha * A @ B^T, A[m][k], B[n][k] row-major fp16.
// CTA tile 128x128 (4 warps, 64x64 warp tile), BK=64, 3-stage cp.async,
// 2 CTAs/SM, fragment double-buffering across k16 chunks.
// ===========================================================================

constexpr int NMAT = 4096;
constexpr int BK = 64;                    // k-tile (128 bytes of fp16)
constexpr int NSTEPS = NMAT / BK;         // 64
constexpr int TILEB = 128 * 128;          // bytes per operand tile
constexpr int STAGE = 2 * TILEB;          // 32 KB
constexpr int NSTAGE = 3;                 // 96 KB smem
constexpr int SMEM_TOTAL = NSTAGE * STAGE;
constexpr int TPAD = 132;                 // transpose buffer row stride (floats)

// ---- device scratch (allocation-free) -------------------------------------
__device__ __half g_sims[(size_t)NMAT * NMAT];  // 32 MB fp16 sims
__device__ __half g_xh[(size_t)NMAT * NMAT];    // fp16(feats)
__device__ __half g_ah[(size_t)NMAT * NMAT];    // fp16(attn)

// ---- helpers --------------------------------------------------------------
#define SWZ(o) ((o) ^ (((o) >> 3) & 0x70))

__device__ __forceinline__ uint32_t smem_u32(const void* p) {
    uint32_t a;
    asm("{ .reg .u64 t; cvta.to.shared.u64 t, %1; cvt.u32.u64 %0, t; }"
        : "=r"(a) : "l"(p));
    return a;
}
__device__ __forceinline__ void cp_async16(uint32_t dst, const void* src) {
    asm volatile("cp.async.cg.shared.global [%0], [%1], 16;"
                 :: "r"(dst), "l"(src));
}
__device__ __forceinline__ void cp_commit() {
    asm volatile("cp.async.commit_group;" ::: "memory");
}
template <int N>
__device__ __forceinline__ void cp_wait() {
    asm volatile("cp.async.wait_group %0;" :: "n"(N) : "memory");
}
__device__ __forceinline__ void ldsm_x4(uint32_t addr, uint32_t r[4]) {
    asm volatile("ldmatrix.sync.aligned.m8n8.x4.shared.b16 {%0,%1,%2,%3}, [%4];"
                 : "=r"(r[0]), "=r"(r[1]), "=r"(r[2]), "=r"(r[3]) : "r"(addr));
}
__device__ __forceinline__ void mma_f16(float d[4], const uint32_t a[4],
                                        uint32_t b0, uint32_t b1) {
    asm volatile(
        "mma.sync.aligned.m16n8k16.row.col.f32.f16.f16.f32 "
        "{%0,%1,%2,%3}, {%4,%5,%6,%7}, {%8,%9}, {%0,%1,%2,%3};"
        : "+f"(d[0]), "+f"(d[1]), "+f"(d[2]), "+f"(d[3])
        : "r"(a[0]), "r"(a[1]), "r"(a[2]), "r"(a[3]), "r"(b0), "r"(b1));
}

// ===========================================================================
// C[128x128] = alpha * A @ B^T.  OutT in {float, __half}.
// MIRROR: compute only by <= bx; off-diagonal tiles also written transposed.
// ===========================================================================
template <bool MIRROR, typename OutT>
__global__ __launch_bounds__(128, 2)
void gemm_f16(const __half* __restrict__ A, const __half* __restrict__ B,
              OutT* __restrict__ C, float alpha)
{
    if (MIRROR && blockIdx.y > blockIdx.x) return;

    extern __shared__ char smem[];
    const uint32_t sbase = smem_u32(smem);

    const int tid  = threadIdx.x;
    const int warp = tid >> 5;
    const int lane = tid & 31;
    const int wm   = (warp & 1) * 64;
    const int wn   = (warp >> 1) * 64;
    const int rowBase = blockIdx.y * 128;
    const int colBase = blockIdx.x * 128;

    const size_t rowB = (size_t)NMAT * 2;
    const char* gA = (const char*)(A + (size_t)rowBase * NMAT);
    const char* gB = (const char*)(B + (size_t)colBase * NMAT);

    const int mA  = (lane & 7) + ((lane >> 3) & 1) * 8;
    const int kAo = ((lane >> 4) & 1) * 16;
    const int nB  = (lane & 7) + ((lane >> 4) & 1) * 8;
    const int kBo = ((lane >> 3) & 1) * 16;

    float acc[4][8][4];
#pragma unroll
    for (int i = 0; i < 4; i++)
#pragma unroll
        for (int j = 0; j < 8; j++)
#pragma unroll
            for (int t = 0; t < 4; t++) acc[i][j][t] = 0.0f;

    auto load_stage = [&](int kt) {
        if (kt < NSTEPS) {
            const uint32_t st = sbase + (kt % NSTAGE) * STAGE;
            const size_t kOff = (size_t)kt * 128;
#pragma unroll
            for (int l = 0; l < 8; l++) {
                const int i = tid + l * 128;
                const int r = i >> 3, c = (i & 7) << 4;
                cp_async16(st + SWZ(r * 128 + c),
                           gA + (size_t)r * rowB + kOff + c);
            }
#pragma unroll
            for (int l = 0; l < 8; l++) {
                const int i = tid + l * 128;
                const int r = i >> 3, c = (i & 7) << 4;
                cp_async16(st + TILEB + SWZ(r * 128 + c),
                           gB + (size_t)r * rowB + kOff + c);
            }
        }
        cp_commit();
    };

    load_stage(0);
    load_stage(1);

    // Double-buffered fragment registers (chunk-level software pipeline)
    uint32_t af[2][4][4], bf[2][4][4];

    for (int kt = 0; kt < NSTEPS; kt++) {
        cp_wait<NSTAGE - 2>();
        __syncthreads();
        load_stage(kt + NSTAGE - 1);

        const uint32_t st = sbase + (kt % NSTAGE) * STAGE;

        // Preload chunk 0 fragments
#pragma unroll
        for (int mi = 0; mi < 4; mi++)
            ldsm_x4(st + SWZ((wm + mi * 16 + mA) * 128 + kAo), af[0][mi]);
#pragma unroll
        for (int nb = 0; nb < 4; nb++)
            ldsm_x4(st + TILEB + SWZ((wn + nb * 16 + nB) * 128 + kBo), bf[0][nb]);

#pragma unroll
        for (int ck = 0; ck < 4; ck++) {
            const int cur = ck & 1, nxt = cur ^ 1;
            if (ck < 3) {  // prefetch next chunk's fragments before the MMAs
                const int kb = (ck + 1) * 32;
#pragma unroll
                for (int mi = 0; mi < 4; mi++)
                    ldsm_x4(st + SWZ((wm + mi * 16 + mA) * 128 + kb + kAo),
                            af[nxt][mi]);
#pragma unroll
                for (int nb = 0; nb < 4; nb++)
                    ldsm_x4(st + TILEB + SWZ((wn + nb * 16 + nB) * 128 + kb + kBo),
                            bf[nxt][nb]);
            }
#pragma unroll
            for (int mi = 0; mi < 4; mi++)
#pragma unroll
                for (int nb = 0; nb < 4; nb++)
#pragma unroll
                    for (int h = 0; h < 2; h++)
                        mma_f16(acc[mi][nb * 2 + h], af[cur][mi],
                                bf[cur][nb][2 * h], bf[cur][nb][2 * h + 1]);
        }
    }

    // ---- scale once ----
#pragma unroll
    for (int mi = 0; mi < 4; mi++)
#pragma unroll
        for (int nj = 0; nj < 8; nj++)
#pragma unroll
            for (int t = 0; t < 4; t++) acc[mi][nj][t] *= alpha;

    // ---- normal store ----
    const int rq = lane >> 2, cq = (lane & 3) * 2;
#pragma unroll
    for (int mi = 0; mi < 4; mi++) {
        const int row0 = rowBase + wm + mi * 16 + rq;
#pragma unroll
        for (int nj = 0; nj < 8; nj++) {
            const int col = colBase + wn + nj * 8 + cq;
            if constexpr (sizeof(OutT) == 4) {
                *(float2*)&C[(size_t)row0 * NMAT + col] =
                    make_float2(acc[mi][nj][0], acc[mi][nj][1]);
                *(float2*)&C[(size_t)(row0 + 8) * NMAT + col] =
                    make_float2(acc[mi][nj][2], acc[mi][nj][3]);
            } else {
                *(__half2*)&C[(size_t)row0 * NMAT + col] =
                    __floats2half2_rn(acc[mi][nj][0], acc[mi][nj][1]);
                *(__half2*)&C[(size_t)(row0 + 8) * NMAT + col] =
                    __floats2half2_rn(acc[mi][nj][2], acc[mi][nj][3]);
            }
        }
    }

    // ---- mirror store (transpose via smem) for off-diagonal tiles ----
    if (MIRROR && blockIdx.x != blockIdx.y) {
        __syncthreads();  // all warps done reading the last stage
        float* T = (float*)smem;  // [128][TPAD] floats = 67.6 KB <= 96 KB
#pragma unroll
        for (int mi = 0; mi < 4; mi++) {
            const int r0 = wm + mi * 16 + rq;
#pragma unroll
            for (int nj = 0; nj < 8; nj++) {
                const int c0 = wn + nj * 8 + cq;
                T[(c0 + 0) * TPAD + r0]     = acc[mi][nj][0];
                T[(c0 + 1) * TPAD + r0]     = acc[mi][nj][1];
                T[(c0 + 0) * TPAD + r0 + 8] = acc[mi][nj][2];
                T[(c0 + 1) * TPAD + r0 + 8] = acc[mi][nj][3];
            }
        }
        __syncthreads();
#pragma unroll 4
        for (int rb = 0; rb < 128; rb += 4) {
            const int rr = rb + warp;
            const float4 v = *(const float4*)&T[rr * TPAD + (lane << 2)];
            if constexpr (sizeof(OutT) == 4) {
                *(float4*)&C[(size_t)(colBase + rr) * NMAT + rowBase + (lane << 2)] = v;
            } else {
                __half2 h0 = __floats2half2_rn(v.x, v.y);
                __half2 h1 = __floats2half2_rn(v.z, v.w);
                *(uint2*)&C[(size_t)(colBase + rr) * NMAT + rowBase + (lane << 2)] =
                    make_uint2(*(uint32_t*)&h0, *(uint32_t*)&h1);
            }
        }
    }
}

// ===========================================================================
// feats fp32 -> fp16
// ===========================================================================
__global__ __launch_bounds__(256)
void conv_f16(const float* __restrict__ x, __half* __restrict__ h)
{
    const size_t i = (size_t)blockIdx.x * blockDim.x + threadIdx.x;
    const float4 v = ((const float4*)x)[i];
    __half2* hp = (__half2*)h;
    hp[2 * i]     = __floats2half2_rn(v.x, v.y);
    hp[2 * i + 1] = __floats2half2_rn(v.z, v.w);
}

// ===========================================================================
// Row softmax over fp16 sims with diag mask; emits fp16 attn.
// ===========================================================================
__global__ __launch_bounds__(256)
void softmax_rows(const __half* __restrict__ S, __half* __restrict__ ah)
{
    const int row = blockIdx.x;
    const int tid = threadIdx.x;
    const __half2* p = (const __half2*)(S + (size_t)row * NMAT);

    float v[16];
    float m = -FLT_MAX;
#pragma unroll
    for (int i = 0; i < 8; i++) {
        const int j2 = tid + i * 256;          // half2 index
        const float2 f = __half22float2(p[j2]);
        v[2 * i] = f.x;
        v[2 * i + 1] = f.y;
        const int j = 2 * j2;
        if (j != row)     m = fmaxf(m, f.x);
        if (j + 1 != row) m = fmaxf(m, f.y);
    }

    __shared__ float red[256];
    red[tid] = m;
    __syncthreads();
#pragma unroll
    for (int s = 128; s > 0; s >>= 1) {
        if (tid < s) red[tid] = fmaxf(red[tid], red[tid + s]);
        __syncthreads();
    }
    m = red[0];
    __syncthreads();

    float sum = 0.0f;
#pragma unroll
    for (int i = 0; i < 8; i++) {
        const int j = 2 * (tid + i * 256);
        float e0 = (j == row)     ? 0.0f : __expf(v[2 * i] - m);
        float e1 = (j + 1 == row) ? 0.0f : __expf(v[2 * i + 1] - m);
        v[2 * i] = e0;
        v[2 * i + 1] = e1;
        sum += e0 + e1;
    }
    red[tid] = sum;
    __syncthreads();
#pragma unroll
    for (int s = 128; s > 0; s >>= 1) {
        if (tid < s) red[tid] += red[tid + s];
        __syncthreads();
    }
    const float inv = 1.0f / red[0];

    __half2* arow = (__half2*)(ah + (size_t)row * NMAT);
#pragma unroll
    for (int i = 0; i < 8; i++) {
        const int j2 = tid + i * 256;
        arow[j2] = __floats2half2_rn(v[2 * i] * inv, v[2 * i + 1] * inv);
    }
}

// ===========================================================================
extern "C" void kernel_launch(void* const* d_in, const int* in_sizes, int n_in,
                              void* d_out, int out_size)
{
    const float* feats = (const float*)d_in[0];
    float* out = (float*)d_out;

    __half *sims, *xh, *ah;
    cudaGetSymbolAddress((void**)&sims, g_sims);
    cudaGetSymbolAddress((void**)&xh, g_xh);
    cudaGetSymbolAddress((void**)&ah, g_ah);

    cudaFuncSetAttribute((void*)gemm_f16<true, __half>,
                         cudaFuncAttributeMaxDynamicSharedMemorySize, SMEM_TOTAL);
    cudaFuncSetAttribute((void*)gemm_f16<false, float>,
                         cudaFuncAttributeMaxDynamicSharedMemorySize, SMEM_TOTAL);

    // 1) feats -> fp16
    conv_f16<<<(NMAT * (size_t)NMAT / 4) / 256, 256>>>(feats, xh);

    dim3 grid(NMAT / 128, NMAT / 128);  // (32, 32)

    // 2) sims = feats @ feats^T / 4096  (symmetric: upper tiles + mirror)
    gemm_f16<true, __half><<<grid, 128, SMEM_TOTAL>>>(xh, xh, sims, 1.0f / 4096.0f);

    // 3) softmax rows (diag masked) -> fp16 attn
    softmax_rows<<<NMAT, 256>>>(sims, ah);

    // 4) out = attn @ feats^T / 64  (full)
    gemm_f16<false, float><<<grid, 128, SMEM_TOTAL>>>(ah, xh, out, 1.0f / 64.0f);
}